// round 2
// baseline (speedup 1.0000x reference)
#include <cuda_runtime.h>
#include <cuda_bf16.h>

// Problem constants
#define BB 8
#define QQ 128
#define KK 512
#define DD 256
#define UU 256
#define TQ 8              // q rows per attention block
#define KCHUNK 64         // kp rows staged in shared per iteration

// Scratch for projections (static device arrays: allowed, no allocation)
__device__ float g_qp[BB * QQ * UU];   // 1 MB
__device__ float g_kp[BB * KK * UU];   // 4 MB

// ---------------------------------------------------------------------------
// tanh via ex2.approx + rcp.approx: tanh(x) = 1 - 2/(exp(2x)+1)
// abs error ~1e-6; handles +/-inf saturation correctly (e=inf -> 1, e=0 -> -1)
// ---------------------------------------------------------------------------
__device__ __forceinline__ float tanh_fast(float x) {
    float e;
    asm("ex2.approx.f32 %0, %1;" : "=f"(e) : "f"(x * 2.885390081777927f)); // 2*log2(e)
    float r;
    asm("rcp.approx.f32 %0, %1;" : "=f"(r) : "f"(e + 1.0f));
    return fmaf(-2.0f, r, 1.0f);
}

// ---------------------------------------------------------------------------
// SGEMM: C[M,256] = A[M,256] @ W[256,256]; BM=BN=64, BK=16, 256 thr, 4x4 tile
// which==0 -> C = g_qp, which==1 -> C = g_kp
// ---------------------------------------------------------------------------
__global__ void proj_gemm(const float* __restrict__ A,
                          const float* __restrict__ W,
                          int which) {
    __shared__ float As[16][68];   // transposed A tile, padded stride (16B aligned)
    __shared__ float Ws[16][64];

    float* C = which ? g_kp : g_qp;

    const int tid = threadIdx.x;
    const int tx = tid & 15;       // 0..15 -> n
    const int ty = tid >> 4;       // 0..15 -> m
    const int m0 = blockIdx.y * 64;
    const int n0 = blockIdx.x * 64;

    const int ar  = tid >> 2;      // 0..63  A row within tile
    const int ac4 = tid & 3;       // 0..3   A float4 within 16-col slab
    const int wr  = tid >> 4;      // 0..15  W row within tile
    const int wc4 = tid & 15;      // 0..15  W float4 within 64-col slab

    float acc[4][4];
#pragma unroll
    for (int i = 0; i < 4; i++)
#pragma unroll
        for (int j = 0; j < 4; j++) acc[i][j] = 0.0f;

    for (int k0 = 0; k0 < DD; k0 += 16) {
        float4 a = *(const float4*)&A[(m0 + ar) * DD + k0 + ac4 * 4];
        float4 w = *(const float4*)&W[(k0 + wr) * UU + n0 + wc4 * 4];
        __syncthreads();
        As[ac4 * 4 + 0][ar] = a.x;
        As[ac4 * 4 + 1][ar] = a.y;
        As[ac4 * 4 + 2][ar] = a.z;
        As[ac4 * 4 + 3][ar] = a.w;
        *(float4*)&Ws[wr][wc4 * 4] = w;
        __syncthreads();
#pragma unroll
        for (int kk = 0; kk < 16; kk++) {
            float4 av = *(const float4*)&As[kk][ty * 4];
            float4 wv = *(const float4*)&Ws[kk][tx * 4];
            float am[4] = {av.x, av.y, av.z, av.w};
            float wn[4] = {wv.x, wv.y, wv.z, wv.w};
#pragma unroll
            for (int i = 0; i < 4; i++)
#pragma unroll
                for (int j = 0; j < 4; j++)
                    acc[i][j] = fmaf(am[i], wn[j], acc[i][j]);
        }
    }
#pragma unroll
    for (int i = 0; i < 4; i++) {
        float4 o = make_float4(acc[i][0], acc[i][1], acc[i][2], acc[i][3]);
        *(float4*)&C[(m0 + ty * 4 + i) * UU + n0 + tx * 4] = o;
    }
}

// ---------------------------------------------------------------------------
// Attention kernel: one block per (b, q-tile of 8). 256 threads.
// Phase 1: scores[8][512] via tanh over swizzled kp chunks.
// Phase 2: warp-per-row masked softmax (mask value -1e6, matching reference).
// Phase 3: out = attn @ value, thread-per-d.
// ---------------------------------------------------------------------------
__global__ void attn_kernel(const float* __restrict__ value,
                            const int* __restrict__ valid_len,
                            const float* __restrict__ v_w,
                            float* __restrict__ out) {
    extern __shared__ float smem[];
    float4* kp_s4 = (float4*)smem;                 // [64][64] float4 (swizzled) 64KB
    float*  qp_s  = smem + KCHUNK * UU;            // [8][256]                   8KB
    float*  v_s   = qp_s + TQ * UU;                // [256]                      1KB
    float*  sc    = v_s + UU;                      // [8][512]                  16KB

    const int tid = threadIdx.x;
    const int b   = blockIdx.x >> 4;
    const int q0  = (blockIdx.x & 15) * TQ;
    const int vl  = __ldg(&valid_len[b]);

    // load qp tile + v_w
    const float4* qpg = (const float4*)(g_qp + (b * QQ + q0) * UU);
    ((float4*)qp_s)[tid]       = qpg[tid];
    ((float4*)qp_s)[tid + 256] = qpg[tid + 256];
    if (tid < 64) ((float4*)v_s)[tid] = ((const float4*)v_w)[tid];

    const int w = tid >> 5;       // warp = q row
    const int l = tid & 31;       // lane
    const float4* qrow4 = (const float4*)(qp_s + w * UU);
    const float4* v_s4  = (const float4*)v_s;

    const int rA = l, rB = 32 + l;
    const int sA = l & 7;         // same swizzle for both rows (32 ^ r keeps low 3 bits)

    for (int c = 0; c < KK / KCHUNK; c++) {
        const int k0 = c * KCHUNK;
        __syncthreads();  // prev compute done (and qp_s/v_s visible on c==0)
        const float4* kg = (const float4*)(g_kp + (b * KK + k0) * UU);
#pragma unroll
        for (int i = 0; i < 16; i++) {
            int idx = tid + i * 256;
            int r = idx >> 6, c4 = idx & 63;
            kp_s4[r * 64 + (c4 ^ (r & 7))] = kg[r * 64 + c4];
        }
        __syncthreads();

        float accA = 0.0f, accB = 0.0f;
#pragma unroll 4
        for (int u4 = 0; u4 < UU / 4; u4++) {
            float4 q4 = qrow4[u4];
            float4 vv = v_s4[u4];
            float4 a4 = kp_s4[rA * 64 + (u4 ^ sA)];
            float4 b4 = kp_s4[rB * 64 + (u4 ^ sA)];
            accA = fmaf(vv.x, tanh_fast(q4.x + a4.x), accA);
            accA = fmaf(vv.y, tanh_fast(q4.y + a4.y), accA);
            accA = fmaf(vv.z, tanh_fast(q4.z + a4.z), accA);
            accA = fmaf(vv.w, tanh_fast(q4.w + a4.w), accA);
            accB = fmaf(vv.x, tanh_fast(q4.x + b4.x), accB);
            accB = fmaf(vv.y, tanh_fast(q4.y + b4.y), accB);
            accB = fmaf(vv.z, tanh_fast(q4.z + b4.z), accB);
            accB = fmaf(vv.w, tanh_fast(q4.w + b4.w), accB);
        }
        sc[w * KK + k0 + l]      = (k0 + l      < vl) ? accA : -1e6f;
        sc[w * KK + k0 + 32 + l] = (k0 + 32 + l < vl) ? accB : -1e6f;
    }

    // ---- softmax: warp w owns row w (row written only by this warp; no block sync needed) ----
    float* row = sc + w * KK;
    float m = -3.0e38f;
#pragma unroll
    for (int i = 0; i < 16; i++) m = fmaxf(m, row[l + 32 * i]);
#pragma unroll
    for (int off = 16; off; off >>= 1) m = fmaxf(m, __shfl_xor_sync(0xffffffffu, m, off));
    float s = 0.0f;
#pragma unroll
    for (int i = 0; i < 16; i++) {
        float ev = __expf(row[l + 32 * i] - m);  // masked: exp(-1e6-m) -> 0
        row[l + 32 * i] = ev;
        s += ev;
    }
#pragma unroll
    for (int off = 16; off; off >>= 1) s += __shfl_xor_sync(0xffffffffu, s, off);
    float inv = 1.0f / s;
#pragma unroll
    for (int i = 0; i < 16; i++) row[l + 32 * i] *= inv;

    __syncthreads();  // all attn rows visible to all threads

    // ---- output: thread tid = feature d ----
    float acc[TQ];
#pragma unroll
    for (int q = 0; q < TQ; q++) acc[q] = 0.0f;
    const float* vb = value + b * KK * DD;
    for (int k = 0; k < KK; k += 4) {
        float v0 = vb[(k + 0) * DD + tid];
        float v1 = vb[(k + 1) * DD + tid];
        float v2 = vb[(k + 2) * DD + tid];
        float v3 = vb[(k + 3) * DD + tid];
#pragma unroll
        for (int q = 0; q < TQ; q++) {
            float4 a = *(const float4*)&sc[q * KK + k];  // broadcast LDS.128
            acc[q] = fmaf(a.x, v0, fmaf(a.y, v1, fmaf(a.z, v2, fmaf(a.w, v3, acc[q]))));
        }
    }
    float* ob = out + (b * QQ + q0) * DD;
#pragma unroll
    for (int q = 0; q < TQ; q++) ob[q * DD + tid] = acc[q];
}

// ---------------------------------------------------------------------------
// Launch
// ---------------------------------------------------------------------------
extern "C" void kernel_launch(void* const* d_in, const int* in_sizes, int n_in,
                              void* d_out, int out_size) {
    const float* query     = (const float*)d_in[0];
    const float* key       = (const float*)d_in[1];
    const float* value     = (const float*)d_in[2];
    const int*   valid_len = (const int*)d_in[3];
    const float* Wq        = (const float*)d_in[4];
    const float* Wk        = (const float*)d_in[5];
    const float* v_w       = (const float*)d_in[6];
    float* out = (float*)d_out;

    const int smem_attn = (KCHUNK * UU + TQ * UU + UU + TQ * KK) * (int)sizeof(float);
    cudaFuncSetAttribute(attn_kernel, cudaFuncAttributeMaxDynamicSharedMemorySize, smem_attn);

    // projections
    proj_gemm<<<dim3(UU / 64, (BB * QQ) / 64), 256>>>(query, Wq, 0);
    proj_gemm<<<dim3(UU / 64, (BB * KK) / 64), 256>>>(key,   Wk, 1);

    // attention
    attn_kernel<<<BB * (QQ / TQ), 256, smem_attn>>>(value, valid_len, v_w, out);
}

// round 4
// speedup vs baseline: 3.1603x; 3.1603x over previous
#include <cuda_runtime.h>
#include <cuda_bf16.h>
#include <cstdint>

// Problem constants
#define BB 8
#define QQ 128
#define KK 512
#define DD 256
#define UU 256
#define TQ 4               // q rows per attention block
#define KC 32              // kp rows per double-buffered chunk

// Scratch for projections (static device arrays: no allocation)
__device__ float g_qp[BB * QQ * UU];   // 1 MB
__device__ float g_kp[BB * KK * UU];   // 4 MB

// single-MUFU tanh (max abs err ~4.9e-4; fine vs 1e-3 output gate)
__device__ __forceinline__ float tanh_approx(float x) {
    float y;
    asm("tanh.approx.f32 %0, %1;" : "=f"(y) : "f"(x));
    return y;
}

__device__ __forceinline__ void cp_async16(uint32_t smem, const void* g) {
    asm volatile("cp.async.cg.shared.global [%0], [%1], 16;\n" :: "r"(smem), "l"(g));
}
__device__ __forceinline__ void cp_commit() { asm volatile("cp.async.commit_group;\n"); }
template <int N>
__device__ __forceinline__ void cp_wait() { asm volatile("cp.async.wait_group %0;\n" :: "n"(N)); }

// ---------------------------------------------------------------------------
// Merged projection GEMM: rows [0,1024) = query@Wq -> g_qp,
//                         rows [1024,5120) = key@Wk -> g_kp.
// BM=64, BN=64, BK=16, 128 threads, 8x4 per-thread tile (FMA-bound, not LDS).
// ---------------------------------------------------------------------------
__global__ __launch_bounds__(128) void proj_gemm(const float* __restrict__ query,
                                                 const float* __restrict__ key,
                                                 const float* __restrict__ Wq,
                                                 const float* __restrict__ Wk) {
    __shared__ float As[16][68];   // transposed A tile, padded
    __shared__ float Ws[16][64];

    const int tid = threadIdx.x;
    const int m0  = blockIdx.y * 64;
    const int n0  = blockIdx.x * 64;

    const float* A; const float* W; float* C;
    if (m0 < BB * QQ) { A = query + (size_t)m0 * DD;            W = Wq; C = g_qp + (size_t)m0 * UU; }
    else              { A = key   + (size_t)(m0 - BB * QQ) * DD; W = Wk; C = g_kp + (size_t)(m0 - BB * QQ) * UU; }

    const int ty = tid >> 4;      // 0..7  -> 8 output rows each
    const int tx = tid & 15;      // 0..15 -> 4 output cols each

    const int ar0 = tid >> 2;           // A f4 row (0..31), second half +32
    const int ac  = (tid & 3) * 4;      // A col base within 16-k slab
    const int wr0 = tid >> 4;           // W row (0..7), second +8
    const int wc  = (tid & 15) * 4;

    float acc[8][4];
#pragma unroll
    for (int i = 0; i < 8; i++)
#pragma unroll
        for (int j = 0; j < 4; j++) acc[i][j] = 0.0f;

    for (int k0 = 0; k0 < DD; k0 += 16) {
        float4 a0 = *(const float4*)&A[(ar0)      * DD + k0 + ac];
        float4 a1 = *(const float4*)&A[(ar0 + 32) * DD + k0 + ac];
        float4 w0 = *(const float4*)&W[(k0 + wr0)     * UU + n0 + wc];
        float4 w1 = *(const float4*)&W[(k0 + wr0 + 8) * UU + n0 + wc];
        __syncthreads();
        As[ac + 0][ar0] = a0.x; As[ac + 1][ar0] = a0.y;
        As[ac + 2][ar0] = a0.z; As[ac + 3][ar0] = a0.w;
        As[ac + 0][ar0 + 32] = a1.x; As[ac + 1][ar0 + 32] = a1.y;
        As[ac + 2][ar0 + 32] = a1.z; As[ac + 3][ar0 + 32] = a1.w;
        *(float4*)&Ws[wr0][wc]     = w0;
        *(float4*)&Ws[wr0 + 8][wc] = w1;
        __syncthreads();
#pragma unroll
        for (int kk = 0; kk < 16; kk++) {
            float4 av0 = *(const float4*)&As[kk][ty * 8];
            float4 av1 = *(const float4*)&As[kk][ty * 8 + 4];
            float4 wv  = *(const float4*)&Ws[kk][tx * 4];
            float am[8] = {av0.x, av0.y, av0.z, av0.w, av1.x, av1.y, av1.z, av1.w};
            float wn[4] = {wv.x, wv.y, wv.z, wv.w};
#pragma unroll
            for (int i = 0; i < 8; i++)
#pragma unroll
                for (int j = 0; j < 4; j++)
                    acc[i][j] = fmaf(am[i], wn[j], acc[i][j]);
        }
    }
#pragma unroll
    for (int i = 0; i < 8; i++) {
        float4 o = make_float4(acc[i][0], acc[i][1], acc[i][2], acc[i][3]);
        *(float4*)&C[(size_t)(ty * 8 + i) * UU + n0 + tx * 4] = o;
    }
}

// ---------------------------------------------------------------------------
// Attention: block = (b, q-tile of 4), 256 threads (8 warps).
// Warp w: q row (w&3), u-half (w>>2). Lane = k within 32-row chunk.
// kp chunks double-buffered via cp.async; chunks beyond valid_len skipped.
// ---------------------------------------------------------------------------
#define SWZ(r, c) ((c) ^ ((r) & 7))

__global__ __launch_bounds__(256) void attn_kernel(const float* __restrict__ value,
                                                   const int* __restrict__ valid_len,
                                                   const float* __restrict__ v_w,
                                                   float* __restrict__ out) {
    extern __shared__ float smem[];
    float4* kb   = (float4*)smem;              // [2][32][64] f4 (swizzled)  64KB
    float*  qp_s = smem + 2 * KC * (UU / 4) * 4; // = smem + 16384            4KB
    float*  v_s  = qp_s + TQ * UU;             //                             1KB
    float*  sc   = v_s + UU;                   // [2][4][512] partials       16KB

    const int tid = threadIdx.x;
    const int b   = blockIdx.x >> 5;
    const int q0  = (blockIdx.x & 31) * TQ;
    const int vl  = __ldg(&valid_len[b]);
    const int w   = tid >> 5, l = tid & 31;
    const int r   = w & 3;         // q row within tile
    const int uh  = w >> 2;        // u half (0/1)

    // stage qp tile + v_w
    const float4* qg = (const float4*)(g_qp + (size_t)(b * QQ + q0) * UU);
    ((float4*)qp_s)[tid] = qg[tid];                       // 256 f4 exactly
    if (tid < 64) ((float4*)v_s)[tid] = ((const float4*)v_w)[tid];

    const float* kpg = g_kp + (size_t)b * KK * UU;
    const uint32_t kb_base = (uint32_t)__cvta_generic_to_shared(kb);

    const int nch = (vl + KC - 1) / KC;   // chunks with any valid k

    // prefetch chunk 0 (nch >= 1 always since vl >= 1)
    {
        const float4* src = (const float4*)kpg;
#pragma unroll
        for (int i = 0; i < 8; i++) {
            int idx = tid + i * 256;
            int rr = idx >> 6, cc = idx & 63;
            cp_async16(kb_base + ((uint32_t)(rr * 64 + SWZ(rr, cc)) << 4), src + idx);
        }
        cp_commit();
    }

    const float4* qrow4 = (const float4*)(qp_s + r * UU);
    const float4* vw4   = (const float4*)v_s;
    const int ubase = uh * 32;

    for (int c = 0; c < nch; c++) {
        if (c + 1 < nch) {
            const float4* src = (const float4*)(kpg + (size_t)(c + 1) * KC * UU);
            const uint32_t bufo = (uint32_t)(((c + 1) & 1) * 2048) << 4;
#pragma unroll
            for (int i = 0; i < 8; i++) {
                int idx = tid + i * 256;
                int rr = idx >> 6, cc = idx & 63;
                cp_async16(kb_base + bufo + ((uint32_t)(rr * 64 + SWZ(rr, cc)) << 4), src + idx);
            }
            cp_commit();
            cp_wait<1>();
        } else {
            cp_wait<0>();
        }
        __syncthreads();   // chunk c visible to all (also covers qp_s/v_s on c==0)

        const float4* kbuf = kb + (c & 1) * 2048 + l * 64;  // this lane's k row
        float acc = 0.0f;
#pragma unroll 8
        for (int j = 0; j < 32; j++) {
            int u4 = ubase + j;
            float4 q4  = qrow4[u4];
            float4 vv  = vw4[u4];
            float4 kk4 = kbuf[SWZ(l, u4)];
            acc = fmaf(vv.x, tanh_approx(q4.x + kk4.x), acc);
            acc = fmaf(vv.y, tanh_approx(q4.y + kk4.y), acc);
            acc = fmaf(vv.z, tanh_approx(q4.z + kk4.z), acc);
            acc = fmaf(vv.w, tanh_approx(q4.w + kk4.w), acc);
        }
        sc[(uh * TQ + r) * KK + c * KC + l] = acc;
        __syncthreads();   // compute done before next iteration's cp.async overwrites
    }

    // ---- masked softmax: warps 0..3, warp w owns row w ----
    if (w < 4) {
        float* rowA = sc + w * KK;             // uh=0 partial (also final attn dest)
        float* rowB = sc + (TQ + w) * KK;      // uh=1 partial
        float vals[16];
        float m = -3.0e38f;
#pragma unroll
        for (int i = 0; i < 16; i++) {
            int k = l + 32 * i;
            float s = (k < vl) ? (rowA[k] + rowB[k]) : -1e6f;
            vals[i] = s;
            m = fmaxf(m, s);
        }
#pragma unroll
        for (int off = 16; off; off >>= 1) m = fmaxf(m, __shfl_xor_sync(0xffffffffu, m, off));
        float ssum = 0.0f;
#pragma unroll
        for (int i = 0; i < 16; i++) {
            float e = __expf(vals[i] - m);
            vals[i] = e;
            ssum += e;
        }
#pragma unroll
        for (int off = 16; off; off >>= 1) ssum += __shfl_xor_sync(0xffffffffu, ssum, off);
        float inv = 1.0f / ssum;
#pragma unroll
        for (int i = 0; i < 16; i++) rowA[l + 32 * i] = vals[i] * inv;
    }
    __syncthreads();

    // ---- output: thread tid = feature d; skip k >= valid_len (attn == 0 there) ----
    float oacc[TQ];
#pragma unroll
    for (int q = 0; q < TQ; q++) oacc[q] = 0.0f;
    const float* vb = value + (size_t)b * KK * DD;
    const int kend = (vl + 3) & ~3;   // attn beyond vl is exactly 0
#pragma unroll 2
    for (int k = 0; k < kend; k += 4) {
        float v0 = vb[(k + 0) * DD + tid];
        float v1 = vb[(k + 1) * DD + tid];
        float v2 = vb[(k + 2) * DD + tid];
        float v3 = vb[(k + 3) * DD + tid];
#pragma unroll
        for (int q = 0; q < TQ; q++) {
            float4 a = *(const float4*)&sc[q * KK + k];   // broadcast LDS.128
            oacc[q] = fmaf(a.x, v0, fmaf(a.y, v1, fmaf(a.z, v2, fmaf(a.w, v3, oacc[q]))));
        }
    }
    float* ob = out + (size_t)(b * QQ + q0) * DD;
#pragma unroll
    for (int q = 0; q < TQ; q++) ob[q * DD + tid] = oacc[q];
}

// ---------------------------------------------------------------------------
// Launch
// ---------------------------------------------------------------------------
extern "C" void kernel_launch(void* const* d_in, const int* in_sizes, int n_in,
                              void* d_out, int out_size) {
    const float* query     = (const float*)d_in[0];
    const float* key       = (const float*)d_in[1];
    const float* value     = (const float*)d_in[2];
    const int*   valid_len = (const int*)d_in[3];
    const float* Wq        = (const float*)d_in[4];
    const float* Wk        = (const float*)d_in[5];
    const float* v_w       = (const float*)d_in[6];
    float* out = (float*)d_out;

    // merged projections: 80 row-tiles x 4 col-tiles
    proj_gemm<<<dim3(UU / 64, (BB * QQ + BB * KK) / 64), 128>>>(query, key, Wq, Wk);

    // attention
    const int smem_attn = (2 * KC * UU + TQ * UU + UU + 2 * TQ * KK) * (int)sizeof(float); // 87KB
    cudaFuncSetAttribute(attn_kernel, cudaFuncAttributeMaxDynamicSharedMemorySize, smem_attn);
    attn_kernel<<<BB * (QQ / TQ), 256, smem_attn>>>(value, valid_len, v_w, out);
}